// round 9
// baseline (speedup 1.0000x reference)
#include <cuda_runtime.h>

// SimpleNetworkAD: 480 independent 1->20->20->20->1 tanh MLPs, B=16384.
// R9 (= R8 resubmit; R8 hit "device busy" infra failure before any launch):
//     software-pipeline the 2 batch points ONE LAYER APART so each stage
//     interleaves p0's matmul (FFMA2, fma pipe) with p1's tanh (MUFU pipe).
//     R7 evidence: runtime == FMA-cycles + MUFU-cycles (phase-serialized);
//     overlapping the pipes should recover the ~199K-cyc MUFU term.
//     Transposed I/O via __device__ scratch kept from R7.

#define GNODE 480
#define HDIM  20
#define TPB   256
#define PTS   2
#define BMAX  16384

typedef unsigned long long u64;

__device__ float g_xT[(size_t)GNODE * BMAX];    // x transposed   [G, B]
__device__ float g_outT[(size_t)GNODE * BMAX];  // out transposed [G, B]

__device__ __forceinline__ u64 f2_pack(float lo, float hi) {
    u64 r; asm("mov.b64 %0, {%1, %2};" : "=l"(r) : "f"(lo), "f"(hi)); return r;
}
__device__ __forceinline__ u64 f2_dup(float v) {
    u64 r; asm("mov.b64 %0, {%1, %1};" : "=l"(r) : "f"(v)); return r;
}
__device__ __forceinline__ void f2_unpack(u64 v, float& lo, float& hi) {
    asm("mov.b64 {%0, %1}, %2;" : "=f"(lo), "=f"(hi) : "l"(v));
}
__device__ __forceinline__ u64 f2_fma(u64 a, u64 b, u64 c) {
    u64 d; asm("fma.rn.f32x2 %0, %1, %2, %3;" : "=l"(d) : "l"(a), "l"(b), "l"(c)); return d;
}
__device__ __forceinline__ float tanha(float x) {
    float r; asm("tanh.approx.f32 %0, %1;" : "=f"(r) : "f"(x)); return r;
}

// ---- Transpose kernels (32x32 tiles, 32x8 threads) ----
#define TD 32
__global__ void transpose_in_kernel(const float* __restrict__ src, int n_b) {
    __shared__ float tile[TD][TD + 1];
    int g = blockIdx.x * TD + threadIdx.x;
    int b = blockIdx.y * TD + threadIdx.y;
    #pragma unroll
    for (int i = 0; i < TD; i += 8)
        if (g < GNODE && (b + i) < n_b)
            tile[threadIdx.y + i][threadIdx.x] = src[(size_t)(b + i) * GNODE + g];
    __syncthreads();
    int b2 = blockIdx.y * TD + threadIdx.x;
    int g2 = blockIdx.x * TD + threadIdx.y;
    #pragma unroll
    for (int i = 0; i < TD; i += 8)
        if (b2 < n_b && (g2 + i) < GNODE)
            g_xT[(size_t)(g2 + i) * n_b + b2] = tile[threadIdx.x][threadIdx.y + i];
}

__global__ void transpose_out_kernel(float* __restrict__ dst, int n_b) {
    __shared__ float tile[TD][TD + 1];
    int b = blockIdx.x * TD + threadIdx.x;
    int g = blockIdx.y * TD + threadIdx.y;
    #pragma unroll
    for (int i = 0; i < TD; i += 8)
        if (b < n_b && (g + i) < GNODE)
            tile[threadIdx.y + i][threadIdx.x] = g_outT[(size_t)(g + i) * n_b + b];
    __syncthreads();
    int g2 = blockIdx.y * TD + threadIdx.x;
    int b2 = blockIdx.x * TD + threadIdx.y;
    #pragma unroll
    for (int i = 0; i < TD; i += 8)
        if (g2 < GNODE && (b2 + i) < n_b)
            dst[(size_t)(b2 + i) * GNODE + g2] = tile[threadIdx.x][threadIdx.y + i];
}

// ---- Main compute: layer-skewed dual-point pipeline ----
__global__ void __launch_bounds__(TPB, 2)
simple_network_ad_kernel(const float* __restrict__ W1, const float* __restrict__ B1,
                         const float* __restrict__ W2, const float* __restrict__ B2,
                         const float* __restrict__ W3, const float* __restrict__ B3,
                         const float* __restrict__ W4, const float* __restrict__ B4,
                         int n_b)
{
    __shared__ __align__(16) float sW1[HDIM], sB1[HDIM];
    __shared__ __align__(16) float sW2[HDIM * HDIM], sB2[HDIM];
    __shared__ __align__(16) float sW3[HDIM * HDIM], sB3[HDIM];
    __shared__ __align__(16) float sW4[HDIM];
    __shared__ float sB4;

    const int g   = blockIdx.y;
    const int tid = threadIdx.x;

    if (tid < HDIM) {
        sW1[tid] = W1[g * HDIM + tid];
        sB1[tid] = B1[g * HDIM + tid];
        sB2[tid] = B2[g * HDIM + tid];
        sB3[tid] = B3[g * HDIM + tid];
        sW4[tid] = W4[g * HDIM + tid];
    }
    if (tid == 0) sB4 = B4[g];
    for (int i = tid; i < HDIM * HDIM; i += TPB) {
        sW2[i] = W2[g * HDIM * HDIM + i];
        sW3[i] = W3[g * HDIM * HDIM + i];
    }
    __syncthreads();

    const int b0 = (blockIdx.x * TPB + tid) * PTS;
    if (b0 >= n_b) return;
    const int b1 = b0 + 1;

    const float4* sW1v = (const float4*)sW1;
    const float4* sB1v = (const float4*)sB1;
    const float4* sW2v = (const float4*)sW2;
    const float4* sB2v = (const float4*)sB2;
    const float4* sW3v = (const float4*)sW3;
    const float4* sB3v = (const float4*)sB3;
    const float4* sW4v = (const float4*)sW4;

    float x0, x1;
    if (b1 < n_b) {
        float2 v = *(const float2*)&g_xT[(size_t)g * n_b + b0];
        x0 = v.x; x1 = v.y;
    } else {
        x0 = g_xT[(size_t)g * n_b + b0]; x1 = 0.0f;
    }

    float h0[HDIM], h1[HDIM];       // activations for p0 / p1
    u64 aP[HDIM / 2], aQ[HDIM / 2]; // pre-activation pairs for p0 / p1

    // ---- S0: L1 pre-act p0 ----
    {
        u64 xd0 = f2_dup(x0);
        #pragma unroll
        for (int q = 0; q < 5; q++) {
            float4 w = sW1v[q], b = sB1v[q];
            aP[2 * q]     = f2_fma(xd0, f2_pack(w.x, w.y), f2_pack(b.x, b.y));
            aP[2 * q + 1] = f2_fma(xd0, f2_pack(w.z, w.w), f2_pack(b.z, b.w));
        }
    }
    // ---- S1: L1 pre-act p1 (FMA)  ||  tanh L1 p0 (MUFU) ----
    {
        u64 xd1 = f2_dup(x1);
        #pragma unroll
        for (int q = 0; q < 5; q++) {
            float4 w = sW1v[q], b = sB1v[q];
            aQ[2 * q]     = f2_fma(xd1, f2_pack(w.x, w.y), f2_pack(b.x, b.y));
            aQ[2 * q + 1] = f2_fma(xd1, f2_pack(w.z, w.w), f2_pack(b.z, b.w));
            float s0, s1;
            f2_unpack(aP[2 * q], s0, s1);
            h0[4 * q] = tanha(s0); h0[4 * q + 1] = tanha(s1);
            f2_unpack(aP[2 * q + 1], s0, s1);
            h0[4 * q + 2] = tanha(s0); h0[4 * q + 3] = tanha(s1);
        }
    }
    // ---- S2: L2 mat p0 (FMA)  ||  tanh L1 p1 (MUFU) ----
    #pragma unroll
    for (int q = 0; q < 5; q++) {
        float4 b = sB2v[q];
        aP[2 * q] = f2_pack(b.x, b.y); aP[2 * q + 1] = f2_pack(b.z, b.w);
    }
    #pragma unroll
    for (int k = 0; k < HDIM; k++) {
        u64 hd = f2_dup(h0[k]);
        #pragma unroll
        for (int q = 0; q < 5; q++) {
            float4 w = sW2v[k * 5 + q];
            aP[2 * q]     = f2_fma(hd, f2_pack(w.x, w.y), aP[2 * q]);
            aP[2 * q + 1] = f2_fma(hd, f2_pack(w.z, w.w), aP[2 * q + 1]);
        }
        if (k < HDIM / 2) {
            float s0, s1;
            f2_unpack(aQ[k], s0, s1);
            h1[2 * k] = tanha(s0); h1[2 * k + 1] = tanha(s1);
        }
    }
    // ---- S3: L2 mat p1 (FMA)  ||  tanh L2 p0 (MUFU) ----
    #pragma unroll
    for (int q = 0; q < 5; q++) {
        float4 b = sB2v[q];
        aQ[2 * q] = f2_pack(b.x, b.y); aQ[2 * q + 1] = f2_pack(b.z, b.w);
    }
    #pragma unroll
    for (int k = 0; k < HDIM; k++) {
        u64 hd = f2_dup(h1[k]);
        #pragma unroll
        for (int q = 0; q < 5; q++) {
            float4 w = sW2v[k * 5 + q];
            aQ[2 * q]     = f2_fma(hd, f2_pack(w.x, w.y), aQ[2 * q]);
            aQ[2 * q + 1] = f2_fma(hd, f2_pack(w.z, w.w), aQ[2 * q + 1]);
        }
        if (k < HDIM / 2) {
            float s0, s1;
            f2_unpack(aP[k], s0, s1);
            h0[2 * k] = tanha(s0); h0[2 * k + 1] = tanha(s1);
        }
    }
    // ---- S4: L3 mat p0 (FMA)  ||  tanh L2 p1 (MUFU) ----
    #pragma unroll
    for (int q = 0; q < 5; q++) {
        float4 b = sB3v[q];
        aP[2 * q] = f2_pack(b.x, b.y); aP[2 * q + 1] = f2_pack(b.z, b.w);
    }
    #pragma unroll
    for (int k = 0; k < HDIM; k++) {
        u64 hd = f2_dup(h0[k]);
        #pragma unroll
        for (int q = 0; q < 5; q++) {
            float4 w = sW3v[k * 5 + q];
            aP[2 * q]     = f2_fma(hd, f2_pack(w.x, w.y), aP[2 * q]);
            aP[2 * q + 1] = f2_fma(hd, f2_pack(w.z, w.w), aP[2 * q + 1]);
        }
        if (k < HDIM / 2) {
            float s0, s1;
            f2_unpack(aQ[k], s0, s1);
            h1[2 * k] = tanha(s0); h1[2 * k + 1] = tanha(s1);
        }
    }
    // ---- S5: L3 mat p1 (FMA)  ||  tanh L3 p0 (MUFU) ----
    #pragma unroll
    for (int q = 0; q < 5; q++) {
        float4 b = sB3v[q];
        aQ[2 * q] = f2_pack(b.x, b.y); aQ[2 * q + 1] = f2_pack(b.z, b.w);
    }
    #pragma unroll
    for (int k = 0; k < HDIM; k++) {
        u64 hd = f2_dup(h1[k]);
        #pragma unroll
        for (int q = 0; q < 5; q++) {
            float4 w = sW3v[k * 5 + q];
            aQ[2 * q]     = f2_fma(hd, f2_pack(w.x, w.y), aQ[2 * q]);
            aQ[2 * q + 1] = f2_fma(hd, f2_pack(w.z, w.w), aQ[2 * q + 1]);
        }
        if (k < HDIM / 2) {
            float s0, s1;
            f2_unpack(aP[k], s0, s1);
            h0[2 * k] = tanha(s0); h0[2 * k + 1] = tanha(s1);
        }
    }
    // ---- S6: L4 dot p0 (FMA)  ||  tanh L3 p1 (MUFU) ----
    u64 o0 = f2_pack(sB4, 0.0f);
    #pragma unroll
    for (int q = 0; q < 5; q++) {
        float4 w = sW4v[q];
        o0 = f2_fma(f2_pack(h0[4 * q], h0[4 * q + 1]), f2_pack(w.x, w.y), o0);
        o0 = f2_fma(f2_pack(h0[4 * q + 2], h0[4 * q + 3]), f2_pack(w.z, w.w), o0);
        float s0, s1;
        f2_unpack(aQ[2 * q], s0, s1);
        h1[4 * q] = tanha(s0); h1[4 * q + 1] = tanha(s1);
        f2_unpack(aQ[2 * q + 1], s0, s1);
        h1[4 * q + 2] = tanha(s0); h1[4 * q + 3] = tanha(s1);
    }
    // ---- S7: L4 dot p1 ----
    u64 o1 = f2_pack(sB4, 0.0f);
    #pragma unroll
    for (int q = 0; q < 5; q++) {
        float4 w = sW4v[q];
        o1 = f2_fma(f2_pack(h1[4 * q], h1[4 * q + 1]), f2_pack(w.x, w.y), o1);
        o1 = f2_fma(f2_pack(h1[4 * q + 2], h1[4 * q + 3]), f2_pack(w.z, w.w), o1);
    }

    float oA, oB, oC, oD;
    f2_unpack(o0, oA, oB);
    f2_unpack(o1, oC, oD);
    if (b1 < n_b) {
        float2 v; v.x = oA + oB; v.y = oC + oD;
        *(float2*)&g_outT[(size_t)g * n_b + b0] = v;
    } else {
        g_outT[(size_t)g * n_b + b0] = oA + oB;
    }
}

// ---- Simple correct fallback for n_b > BMAX (never expected to run) ----
__global__ void simple_network_ad_fallback(const float* __restrict__ x,
                         const float* __restrict__ W1, const float* __restrict__ B1,
                         const float* __restrict__ W2, const float* __restrict__ B2,
                         const float* __restrict__ W3, const float* __restrict__ B3,
                         const float* __restrict__ W4, const float* __restrict__ B4,
                         float* __restrict__ out, int n_b)
{
    int idx = blockIdx.x * blockDim.x + threadIdx.x;
    if (idx >= n_b * GNODE) return;
    int b = idx / GNODE, g = idx % GNODE;
    float xv = x[(size_t)b * GNODE + g];
    float h[HDIM], t[HDIM];
    for (int i = 0; i < HDIM; i++)
        h[i] = tanhf(xv * W1[g * HDIM + i] + B1[g * HDIM + i]);
    for (int l = 0; l < HDIM; l++) {
        float s = B2[g * HDIM + l];
        for (int k = 0; k < HDIM; k++) s += h[k] * W2[g * HDIM * HDIM + k * HDIM + l];
        t[l] = tanhf(s);
    }
    for (int l = 0; l < HDIM; l++) {
        float s = B3[g * HDIM + l];
        for (int k = 0; k < HDIM; k++) s += t[k] * W3[g * HDIM * HDIM + k * HDIM + l];
        h[l] = tanhf(s);
    }
    float o = B4[g];
    for (int k = 0; k < HDIM; k++) o += h[k] * W4[g * HDIM + k];
    out[(size_t)b * GNODE + g] = o;
}

extern "C" void kernel_launch(void* const* d_in, const int* in_sizes, int n_in,
                              void* d_out, int out_size)
{
    const float* x  = (const float*)d_in[0];
    const float* W1 = (const float*)d_in[1];
    const float* B1 = (const float*)d_in[2];
    const float* W2 = (const float*)d_in[3];
    const float* B2 = (const float*)d_in[4];
    const float* W3 = (const float*)d_in[5];
    const float* B3 = (const float*)d_in[6];
    const float* W4 = (const float*)d_in[7];
    const float* B4 = (const float*)d_in[8];
    float* out = (float*)d_out;

    int n_b = in_sizes[0] / GNODE;                      // 16384

    if (n_b <= BMAX) {
        dim3 tgrid_in((GNODE + TD - 1) / TD, (n_b + TD - 1) / TD);
        transpose_in_kernel<<<tgrid_in, dim3(TD, 8)>>>(x, n_b);

        int chunks = (n_b + TPB * PTS - 1) / (TPB * PTS);
        dim3 grid(chunks, GNODE);
        simple_network_ad_kernel<<<grid, TPB>>>(W1, B1, W2, B2, W3, B3, W4, B4, n_b);

        dim3 tgrid_out((n_b + TD - 1) / TD, (GNODE + TD - 1) / TD);
        transpose_out_kernel<<<tgrid_out, dim3(TD, 8)>>>(out, n_b);
    } else {
        int total = n_b * GNODE;
        simple_network_ad_fallback<<<(total + 255) / 256, 256>>>(
            x, W1, B1, W2, B2, W3, B3, W4, B4, out, n_b);
    }
}

// round 11
// speedup vs baseline: 1.5500x; 1.5500x over previous
#include <cuda_runtime.h>

// SimpleNetworkAD: 480 independent 1->20->20->20->1 tanh MLPs, B=16384.
// R11 (= R10 resubmit; R10 hit GPU-acquisition timeout, never ran):
//      JIT-tanh pipelining. R9 showed doubling LDS (split k-loops) is fatal;
//      LDS issue ~= fma pipe in cost. Keep R7's single merged k-loop per layer
//      (shared weight loads for both points) and interleave the PREVIOUS
//      layer's tanh (MUFU) into it just-in-time: prologue produces h[0..5];
//      iteration k<7 produces h[2(k+3)], h[2(k+3)+1]. FMA + MUFU coexist in
//      every basic block; LDS count unchanged vs the 288us R7 kernel.

#define GNODE 480
#define HDIM  20
#define TPB   256
#define PTS   2
#define BMAX  16384

typedef unsigned long long u64;

__device__ float g_xT[(size_t)GNODE * BMAX];    // x transposed   [G, B]
__device__ float g_outT[(size_t)GNODE * BMAX];  // out transposed [G, B]

__device__ __forceinline__ u64 f2_pack(float lo, float hi) {
    u64 r; asm("mov.b64 %0, {%1, %2};" : "=l"(r) : "f"(lo), "f"(hi)); return r;
}
__device__ __forceinline__ u64 f2_dup(float v) {
    u64 r; asm("mov.b64 %0, {%1, %1};" : "=l"(r) : "f"(v)); return r;
}
__device__ __forceinline__ void f2_unpack(u64 v, float& lo, float& hi) {
    asm("mov.b64 {%0, %1}, %2;" : "=f"(lo), "=f"(hi) : "l"(v));
}
__device__ __forceinline__ u64 f2_fma(u64 a, u64 b, u64 c) {
    u64 d; asm("fma.rn.f32x2 %0, %1, %2, %3;" : "=l"(d) : "l"(a), "l"(b), "l"(c)); return d;
}
__device__ __forceinline__ float tanha(float x) {
    float r; asm("tanh.approx.f32 %0, %1;" : "=f"(r) : "f"(x)); return r;
}

// ---- Transpose kernels (32x32 tiles, 32x8 threads) ----
#define TD 32
__global__ void transpose_in_kernel(const float* __restrict__ src, int n_b) {
    __shared__ float tile[TD][TD + 1];
    int g = blockIdx.x * TD + threadIdx.x;
    int b = blockIdx.y * TD + threadIdx.y;
    #pragma unroll
    for (int i = 0; i < TD; i += 8)
        if (g < GNODE && (b + i) < n_b)
            tile[threadIdx.y + i][threadIdx.x] = src[(size_t)(b + i) * GNODE + g];
    __syncthreads();
    int b2 = blockIdx.y * TD + threadIdx.x;
    int g2 = blockIdx.x * TD + threadIdx.y;
    #pragma unroll
    for (int i = 0; i < TD; i += 8)
        if (b2 < n_b && (g2 + i) < GNODE)
            g_xT[(size_t)(g2 + i) * n_b + b2] = tile[threadIdx.x][threadIdx.y + i];
}

__global__ void transpose_out_kernel(float* __restrict__ dst, int n_b) {
    __shared__ float tile[TD][TD + 1];
    int b = blockIdx.x * TD + threadIdx.x;
    int g = blockIdx.y * TD + threadIdx.y;
    #pragma unroll
    for (int i = 0; i < TD; i += 8)
        if (b < n_b && (g + i) < GNODE)
            tile[threadIdx.y + i][threadIdx.x] = g_outT[(size_t)(g + i) * n_b + b];
    __syncthreads();
    int g2 = blockIdx.y * TD + threadIdx.x;
    int b2 = blockIdx.x * TD + threadIdx.y;
    #pragma unroll
    for (int i = 0; i < TD; i += 8)
        if (g2 < GNODE && (b2 + i) < n_b)
            dst[(size_t)(b2 + i) * GNODE + g2] = tile[threadIdx.x][threadIdx.y + i];
}

// Produce h[2j], h[2j+1] for both points from pre-act pair arrays.
#define PRODUCE_H(hA, hB, aA, aB, j) do {                      \
    float _s0, _s1;                                            \
    f2_unpack((aA)[j], _s0, _s1);                              \
    (hA)[2 * (j)] = tanha(_s0); (hA)[2 * (j) + 1] = tanha(_s1);\
    f2_unpack((aB)[j], _s0, _s1);                              \
    (hB)[2 * (j)] = tanha(_s0); (hB)[2 * (j) + 1] = tanha(_s1);\
} while (0)

// ---- Main compute ----
__global__ void __launch_bounds__(TPB, 2)
simple_network_ad_kernel(const float* __restrict__ W1, const float* __restrict__ B1,
                         const float* __restrict__ W2, const float* __restrict__ B2,
                         const float* __restrict__ W3, const float* __restrict__ B3,
                         const float* __restrict__ W4, const float* __restrict__ B4,
                         int n_b)
{
    __shared__ __align__(16) float sW1[HDIM], sB1[HDIM];
    __shared__ __align__(16) float sW2[HDIM * HDIM], sB2[HDIM];
    __shared__ __align__(16) float sW3[HDIM * HDIM], sB3[HDIM];
    __shared__ __align__(16) float sW4[HDIM];
    __shared__ float sB4;

    const int g   = blockIdx.y;
    const int tid = threadIdx.x;

    if (tid < HDIM) {
        sW1[tid] = W1[g * HDIM + tid];
        sB1[tid] = B1[g * HDIM + tid];
        sB2[tid] = B2[g * HDIM + tid];
        sB3[tid] = B3[g * HDIM + tid];
        sW4[tid] = W4[g * HDIM + tid];
    }
    if (tid == 0) sB4 = B4[g];
    for (int i = tid; i < HDIM * HDIM; i += TPB) {
        sW2[i] = W2[g * HDIM * HDIM + i];
        sW3[i] = W3[g * HDIM * HDIM + i];
    }
    __syncthreads();

    const int b0 = (blockIdx.x * TPB + tid) * PTS;
    if (b0 >= n_b) return;
    const int b1 = b0 + 1;

    const float4* sW1v = (const float4*)sW1;
    const float4* sB1v = (const float4*)sB1;
    const float4* sW2v = (const float4*)sW2;
    const float4* sB2v = (const float4*)sB2;
    const float4* sW3v = (const float4*)sW3;
    const float4* sB3v = (const float4*)sB3;
    const float4* sW4v = (const float4*)sW4;

    float x0, x1;
    if (b1 < n_b) {
        float2 v = *(const float2*)&g_xT[(size_t)g * n_b + b0];
        x0 = v.x; x1 = v.y;
    } else {
        x0 = g_xT[(size_t)g * n_b + b0]; x1 = 0.0f;
    }

    float h0[HDIM], h1[HDIM];         // activations (p0 / p1)
    u64 a0[HDIM / 2], a1[HDIM / 2];   // pre-act pairs, bank A
    u64 c0[HDIM / 2], c1[HDIM / 2];   // pre-act pairs, bank C

    // ---- L1 pre-acts -> bank A ----
    {
        u64 xd0 = f2_dup(x0), xd1 = f2_dup(x1);
        #pragma unroll
        for (int q = 0; q < 5; q++) {
            float4 w = sW1v[q], b = sB1v[q];
            u64 wp0 = f2_pack(w.x, w.y), wp1 = f2_pack(w.z, w.w);
            u64 bp0 = f2_pack(b.x, b.y), bp1 = f2_pack(b.z, b.w);
            a0[2 * q]     = f2_fma(xd0, wp0, bp0);
            a0[2 * q + 1] = f2_fma(xd0, wp1, bp1);
            a1[2 * q]     = f2_fma(xd1, wp0, bp0);
            a1[2 * q + 1] = f2_fma(xd1, wp1, bp1);
        }
    }

    // ---- L2: acc -> bank C, JIT tanh(L1) from bank A ----
    #pragma unroll
    for (int j = 0; j < 3; j++) PRODUCE_H(h0, h1, a0, a1, j);
    #pragma unroll
    for (int q = 0; q < 5; q++) {
        float4 b = sB2v[q];
        c0[2 * q] = f2_pack(b.x, b.y); c0[2 * q + 1] = f2_pack(b.z, b.w);
        c1[2 * q] = c0[2 * q];         c1[2 * q + 1] = c0[2 * q + 1];
    }
    #pragma unroll
    for (int k = 0; k < HDIM; k++) {
        u64 hd0 = f2_dup(h0[k]), hd1 = f2_dup(h1[k]);
        #pragma unroll
        for (int q = 0; q < 5; q++) {
            float4 w = sW2v[k * 5 + q];
            u64 wp0 = f2_pack(w.x, w.y), wp1 = f2_pack(w.z, w.w);
            c0[2 * q]     = f2_fma(hd0, wp0, c0[2 * q]);
            c0[2 * q + 1] = f2_fma(hd0, wp1, c0[2 * q + 1]);
            c1[2 * q]     = f2_fma(hd1, wp0, c1[2 * q]);
            c1[2 * q + 1] = f2_fma(hd1, wp1, c1[2 * q + 1]);
        }
        if (k < 7) PRODUCE_H(h0, h1, a0, a1, k + 3);
    }

    // ---- L3: acc -> bank A (reused), JIT tanh(L2) from bank C ----
    #pragma unroll
    for (int j = 0; j < 3; j++) PRODUCE_H(h0, h1, c0, c1, j);
    #pragma unroll
    for (int q = 0; q < 5; q++) {
        float4 b = sB3v[q];
        a0[2 * q] = f2_pack(b.x, b.y); a0[2 * q + 1] = f2_pack(b.z, b.w);
        a1[2 * q] = a0[2 * q];         a1[2 * q + 1] = a0[2 * q + 1];
    }
    #pragma unroll
    for (int k = 0; k < HDIM; k++) {
        u64 hd0 = f2_dup(h0[k]), hd1 = f2_dup(h1[k]);
        #pragma unroll
        for (int q = 0; q < 5; q++) {
            float4 w = sW3v[k * 5 + q];
            u64 wp0 = f2_pack(w.x, w.y), wp1 = f2_pack(w.z, w.w);
            a0[2 * q]     = f2_fma(hd0, wp0, a0[2 * q]);
            a0[2 * q + 1] = f2_fma(hd0, wp1, a0[2 * q + 1]);
            a1[2 * q]     = f2_fma(hd1, wp0, a1[2 * q]);
            a1[2 * q + 1] = f2_fma(hd1, wp1, a1[2 * q + 1]);
        }
        if (k < 7) PRODUCE_H(h0, h1, c0, c1, k + 3);
    }

    // ---- L4: dot, JIT tanh(L3) from bank A ----
    PRODUCE_H(h0, h1, a0, a1, 0);
    PRODUCE_H(h0, h1, a0, a1, 1);
    u64 o0 = f2_pack(sB4, 0.0f), o1 = f2_pack(sB4, 0.0f);
    #pragma unroll
    for (int q = 0; q < 5; q++) {
        float4 w = sW4v[q];
        u64 wp0 = f2_pack(w.x, w.y), wp1 = f2_pack(w.z, w.w);
        o0 = f2_fma(f2_pack(h0[4 * q], h0[4 * q + 1]), wp0, o0);
        o1 = f2_fma(f2_pack(h1[4 * q], h1[4 * q + 1]), wp0, o1);
        if (2 * q + 2 < 10) PRODUCE_H(h0, h1, a0, a1, 2 * q + 2);
        o0 = f2_fma(f2_pack(h0[4 * q + 2], h0[4 * q + 3]), wp1, o0);
        o1 = f2_fma(f2_pack(h1[4 * q + 2], h1[4 * q + 3]), wp1, o1);
        if (2 * q + 3 < 10) PRODUCE_H(h0, h1, a0, a1, 2 * q + 3);
    }

    float oA, oB, oC, oD;
    f2_unpack(o0, oA, oB);
    f2_unpack(o1, oC, oD);
    if (b1 < n_b) {
        float2 v; v.x = oA + oB; v.y = oC + oD;
        *(float2*)&g_outT[(size_t)g * n_b + b0] = v;
    } else {
        g_outT[(size_t)g * n_b + b0] = oA + oB;
    }
}

// ---- Simple correct fallback for n_b > BMAX (never expected to run) ----
__global__ void simple_network_ad_fallback(const float* __restrict__ x,
                         const float* __restrict__ W1, const float* __restrict__ B1,
                         const float* __restrict__ W2, const float* __restrict__ B2,
                         const float* __restrict__ W3, const float* __restrict__ B3,
                         const float* __restrict__ W4, const float* __restrict__ B4,
                         float* __restrict__ out, int n_b)
{
    int idx = blockIdx.x * blockDim.x + threadIdx.x;
    if (idx >= n_b * GNODE) return;
    int b = idx / GNODE, g = idx % GNODE;
    float xv = x[(size_t)b * GNODE + g];
    float h[HDIM], t[HDIM];
    for (int i = 0; i < HDIM; i++)
        h[i] = tanhf(xv * W1[g * HDIM + i] + B1[g * HDIM + i]);
    for (int l = 0; l < HDIM; l++) {
        float s = B2[g * HDIM + l];
        for (int k = 0; k < HDIM; k++) s += h[k] * W2[g * HDIM * HDIM + k * HDIM + l];
        t[l] = tanhf(s);
    }
    for (int l = 0; l < HDIM; l++) {
        float s = B3[g * HDIM + l];
        for (int k = 0; k < HDIM; k++) s += t[k] * W3[g * HDIM * HDIM + k * HDIM + l];
        h[l] = tanhf(s);
    }
    float o = B4[g];
    for (int k = 0; k < HDIM; k++) o += h[k] * W4[g * HDIM + k];
    out[(size_t)b * GNODE + g] = o;
}

extern "C" void kernel_launch(void* const* d_in, const int* in_sizes, int n_in,
                              void* d_out, int out_size)
{
    const float* x  = (const float*)d_in[0];
    const float* W1 = (const float*)d_in[1];
    const float* B1 = (const float*)d_in[2];
    const float* W2 = (const float*)d_in[3];
    const float* B2 = (const float*)d_in[4];
    const float* W3 = (const float*)d_in[5];
    const float* B3 = (const float*)d_in[6];
    const float* W4 = (const float*)d_in[7];
    const float* B4 = (const float*)d_in[8];
    float* out = (float*)d_out;

    int n_b = in_sizes[0] / GNODE;                      // 16384

    if (n_b <= BMAX) {
        dim3 tgrid_in((GNODE + TD - 1) / TD, (n_b + TD - 1) / TD);
        transpose_in_kernel<<<tgrid_in, dim3(TD, 8)>>>(x, n_b);

        int chunks = (n_b + TPB * PTS - 1) / (TPB * PTS);
        dim3 grid(chunks, GNODE);
        simple_network_ad_kernel<<<grid, TPB>>>(W1, B1, W2, B2, W3, B3, W4, B4, n_b);

        dim3 tgrid_out((n_b + TD - 1) / TD, (GNODE + TD - 1) / TD);
        transpose_out_kernel<<<tgrid_out, dim3(TD, 8)>>>(out, n_b);
    } else {
        int total = n_b * GNODE;
        simple_network_ad_fallback<<<(total + 255) / 256, 256>>>(
            x, W1, B1, W2, B2, W3, B3, W4, B4, out, n_b);
    }
}